// round 16
// baseline (speedup 1.0000x reference)
#include <cuda_runtime.h>
#include <cuda_fp16.h>
#include <cstdint>

// v16: counting-sort edges by c; edge kernel on sorted tiles with run-reduction
// epilogue (atomics ~25x fewer). Edge math: fp16 single-pass (R11). Node: R8.
#define N_MAX 16384
#define E_MAX (1 << 20)
#define SC    128
#define RED   32
#define PWN   32
#define PAIR  128
#define XDIM  96

#define TPB  256
#define ETPB 512
#define TS   128
#define PX   136
#define H2LD 132

__device__ __half g_t_h[(size_t)N_MAX * RED];
__device__ float  g_tmp[(size_t)N_MAX * PAIR];
__device__ int    g_hist[N_MAX];
__device__ int    g_cursor[N_MAX];
__device__ int    g_sorted[E_MAX];

// ---------------------------------------------------------------------------
// helpers
// ---------------------------------------------------------------------------
__device__ __forceinline__ uint32_t sm32(const void* p) {
    uint32_t a;
    asm("{ .reg .u64 t; cvta.to.shared.u64 t, %1; cvt.u32.u64 %0, t; }" : "=r"(a) : "l"(p));
    return a;
}
__device__ __forceinline__ void ldmx4(uint32_t& r0, uint32_t& r1, uint32_t& r2,
                                      uint32_t& r3, uint32_t addr) {
    asm volatile("ldmatrix.sync.aligned.m8n8.x4.shared.b16 {%0,%1,%2,%3}, [%4];"
                 : "=r"(r0), "=r"(r1), "=r"(r2), "=r"(r3) : "r"(addr));
}
__device__ __forceinline__ void mma16(float* c, const uint32_t* a, const uint32_t* b) {
    asm volatile(
        "mma.sync.aligned.m16n8k16.row.col.f32.f16.f16.f32 "
        "{%0,%1,%2,%3}, {%4,%5,%6,%7}, {%8,%9}, {%0,%1,%2,%3};"
        : "+f"(c[0]), "+f"(c[1]), "+f"(c[2]), "+f"(c[3])
        : "r"(a[0]), "r"(a[1]), "r"(a[2]), "r"(a[3]), "r"(b[0]), "r"(b[1]));
}
__device__ __forceinline__ uint16_t f2h(float x) {
    __half h = __float2half_rn(x);
    return *(uint16_t*)&h;
}
__device__ __forceinline__ uint32_t pk2(uint16_t a, uint16_t b) {
    return (uint32_t)a | ((uint32_t)b << 16);
}
struct LaneMap { int a_row, a_col, b_row, b_col; };

// ---------------------------------------------------------------------------
// setup kernels
// ---------------------------------------------------------------------------
__global__ void clear_accum_kernel(int total, int nbins) {
    int i = blockIdx.x * blockDim.x + threadIdx.x;
    if (i < total) g_tmp[i] = 0.0f;
    if (i < nbins) g_hist[i] = 0;
}

__global__ void hist_kernel(const int* __restrict__ c_idx, int E) {
    int i = blockIdx.x * blockDim.x + threadIdx.x;
    if (i < E) atomicAdd(&g_hist[c_idx[i]], 1);
}

// single-block exclusive scan over nbins -> g_cursor
__global__ void scan_kernel(int nbins) {
    __shared__ int buf[1024];
    __shared__ int carry;
    const int tid = threadIdx.x;
    if (tid == 0) carry = 0;
    __syncthreads();
    for (int base = 0; base < nbins; base += 1024) {
        int i = base + tid;
        int v = (i < nbins) ? g_hist[i] : 0;
        buf[tid] = v;
        __syncthreads();
        for (int off = 1; off < 1024; off <<= 1) {
            int t = (tid >= off) ? buf[tid - off] : 0;
            __syncthreads();
            buf[tid] += t;
            __syncthreads();
        }
        int excl = buf[tid] - v + carry;
        if (i < nbins) g_cursor[i] = excl;
        __syncthreads();              // all carry reads done
        if (tid == 1023) carry += buf[1023];
        __syncthreads();              // carry visible; buf reusable
    }
}

__global__ void scatter_kernel(const int* __restrict__ c_idx, int E) {
    int i = blockIdx.x * blockDim.x + threadIdx.x;
    if (i < E) {
        int p = atomicAdd(&g_cursor[c_idx[i]], 1);
        g_sorted[p] = i;
    }
}

// ---------------------------------------------------------------------------
// Kernel 1: t = relu(infeats @ W_rd + b_rd), stored fp16
// ---------------------------------------------------------------------------
__global__ __launch_bounds__(TPB, 1)
void reduce_kernel(const float* __restrict__ infeats,
                   const float* __restrict__ W_rd,
                   const float* __restrict__ b_rd, int N) {
    __shared__ float Ws[SC * RED];
    __shared__ float rows[8 * SC];
    const int tid = threadIdx.x;
    const int base = blockIdx.x * 8;
    for (int i = tid; i < SC * RED; i += TPB) Ws[i] = W_rd[i];
    for (int i = tid; i < 8 * SC; i += TPB) {
        int nl = i >> 7, k = i & 127;
        rows[i] = (base + nl < N) ? infeats[(size_t)(base + nl) * SC + k] : 0.0f;
    }
    __syncthreads();
    const int nl = tid >> 5, r = tid & 31;
    float acc = b_rd[r];
#pragma unroll 8
    for (int i = 0; i < SC; i++) acc += rows[nl * SC + i] * Ws[i * RED + r];
    if (base + nl < N)
        g_t_h[(size_t)(base + nl) * RED + r] = __float2half_rn(fmaxf(acc, 0.0f));
}

// ---------------------------------------------------------------------------
// Kernel 2: fused edge MLP on SORTED edges + run-reduction scatter.
// 512 threads / 16 warps; warp strip = 32 rows x 32 cols.
// ---------------------------------------------------------------------------
#define WPLANE_B (128 * PX * 2)              // 34816
#define OFF_X   0
#define OFF_W0  (OFF_X + WPLANE_B)
#define OFF_W1  (OFF_W0 + WPLANE_B)
#define OFF_H2  (OFF_W1 + WPLANE_B)          // fp32 128 x 132
#define OFF_CS  (OFF_H2 + TS * H2LD * 4)
#define OFF_NS  (OFF_CS + 512)
#define OFF_ES  (OFF_NS + 512)
#define OFF_B0  (OFF_ES + 512)
#define OFF_B1  (OFF_B0 + 512)
#define EDGE_SMEM_BYTES (OFF_B1 + 512)       // ~175 KB

template <int KS>
__device__ __forceinline__ void gemm_strip(uint32_t x, uint32_t w,
                                           int wrow, int wcol, LaneMap lm,
                                           float acc[2][4][4]) {
#pragma unroll
    for (int m = 0; m < 2; m++)
#pragma unroll
        for (int n = 0; n < 4; n++)
#pragma unroll
            for (int i = 0; i < 4; i++) acc[m][n][i] = 0.f;

#pragma unroll 2
    for (int ks = 0; ks < KS; ks++) {
        const int k0 = ks * 16;
        uint32_t A[2][4];
#pragma unroll
        for (int m = 0; m < 2; m++) {
            uint32_t off = (uint32_t)((wrow + m * 16 + lm.a_row) * PX + k0 + lm.a_col) * 2;
            ldmx4(A[m][0], A[m][1], A[m][2], A[m][3], x + off);
        }
        uint32_t B[4][2];
#pragma unroll
        for (int nn = 0; nn < 2; nn++) {
            uint32_t off = (uint32_t)((wcol + nn * 16 + lm.b_row) * PX + k0 + lm.b_col) * 2;
            uint32_t r0, r1, r2, r3;
            ldmx4(r0, r1, r2, r3, w + off);
            B[nn * 2][0] = r0;     B[nn * 2][1] = r1;
            B[nn * 2 + 1][0] = r2; B[nn * 2 + 1][1] = r3;
        }
#pragma unroll
        for (int m = 0; m < 2; m++)
#pragma unroll
            for (int n = 0; n < 4; n++)
                mma16(acc[m][n], A[m], B[n]);
    }
}

__global__ __launch_bounds__(ETPB, 1)
void edge_kernel(const float* __restrict__ pw,
                 const int* __restrict__ c_idx,
                 const int* __restrict__ n_idx,
                 const float* __restrict__ W0, const float* __restrict__ b0,
                 const float* __restrict__ W1, const float* __restrict__ b1,
                 int E, int ntiles) {
    extern __shared__ char smem[];
    const uint32_t sb = sm32(smem);
    const uint32_t x  = sb + OFF_X;
    const uint32_t w0 = sb + OFF_W0;
    const uint32_t w1 = sb + OFF_W1;
    float* h2f = (float*)(smem + OFF_H2);
    int*   cs  = (int*)(smem + OFF_CS);
    int*   ns  = (int*)(smem + OFF_NS);
    int*   es  = (int*)(smem + OFF_ES);
    float* b0s = (float*)(smem + OFF_B0);
    float* b1s = (float*)(smem + OFF_B1);

    const int tid = threadIdx.x;
    const int wid = tid >> 5, lid = tid & 31;
    const int wrow = (wid & 3) * 32;
    const int wcol = (wid >> 2) * 32;
    const int g = lid >> 2, t = lid & 3;

    LaneMap lm;
    lm.a_row = (lid & 7) + ((lid >> 3) & 1) * 8;
    lm.a_col = ((lid >> 4) & 1) * 8;
    lm.b_row = (lid & 7) + ((lid >> 4) & 1) * 8;
    lm.b_col = ((lid >> 3) & 1) * 8;

    for (int idx = tid; idx < XDIM * PAIR; idx += ETPB) {
        int k = idx >> 7, j = idx & 127;
        *(uint16_t*)(smem + OFF_W0 + (uint32_t)(j * PX + k) * 2) = f2h(W0[idx]);
    }
    for (int idx = tid; idx < PAIR * PAIR; idx += ETPB) {
        int k = idx >> 7, j = idx & 127;
        *(uint16_t*)(smem + OFF_W1 + (uint32_t)(j * PX + k) * 2) = f2h(W1[idx]);
    }
    if (tid < PAIR) { b0s[tid] = b0[tid]; b1s[tid] = b1[tid]; }

    for (int tile = blockIdx.x; tile < ntiles; tile += gridDim.x) {
        const int base = tile * TS;
        const int nvalid = min(TS, E - base);
        __syncthreads();   // previous tile fully consumed
        if (tid < TS) {
            if (tid < nvalid) {
                int eid = g_sorted[base + tid];
                es[tid] = eid;
                cs[tid] = c_idx[eid];
                ns[tid] = n_idx[eid];
            } else {
                es[tid] = -1; cs[tid] = -1; ns[tid] = -1;
            }
        }
        __syncthreads();

        // gather X (sorted edges): pw fp32->fp16, node feats fp16 copies
        for (int idx = tid; idx < TS * 16; idx += ETPB) {
            int r = idx >> 4, gg = idx & 15;
            if (gg < 8) {
                float4 v = make_float4(0.f, 0.f, 0.f, 0.f);
                int eid = es[r];
                if (eid >= 0)
                    v = *(const float4*)&pw[(size_t)eid * PWN + gg * 4];
                uint32_t o = (uint32_t)(r * PX + gg * 4) * 2;
                *(uint2*)(smem + OFF_X + o) =
                    make_uint2(pk2(f2h(v.x), f2h(v.y)), pk2(f2h(v.z), f2h(v.w)));
            } else {
                int hi = gg - 8;
                uint4 v = make_uint4(0u, 0u, 0u, 0u);
                int c = cs[r];
                if (c >= 0) {
                    if (hi < 4) {
                        v = *(const uint4*)&g_t_h[(size_t)c * RED + hi * 8];
                    } else {
                        int n = ns[r];
                        if (n != c)
                            v = *(const uint4*)&g_t_h[(size_t)n * RED + (hi - 4) * 8];
                    }
                }
                uint32_t col = 32 + hi * 8;
                *(uint4*)(smem + OFF_X + (uint32_t)(r * PX + col) * 2) = v;
            }
        }
        __syncthreads();

        // GEMM1: K = 96
        float acc[2][4][4];
        gemm_strip<6>(x, w0, wrow, wcol, lm, acc);
        __syncthreads();

        // epilogue 1: relu(acc+b0) -> fp16 H1 (in place of X)
#pragma unroll
        for (int m = 0; m < 2; m++) {
            const int r0 = wrow + m * 16 + g;
#pragma unroll
            for (int n = 0; n < 4; n++) {
                const int col = wcol + n * 8 + t * 2;
                const float bx = b0s[col], by = b0s[col + 1];
                float v0 = fmaxf(acc[m][n][0] + bx, 0.f);
                float v1 = fmaxf(acc[m][n][1] + by, 0.f);
                float v2 = fmaxf(acc[m][n][2] + bx, 0.f);
                float v3 = fmaxf(acc[m][n][3] + by, 0.f);
                uint32_t o0 = (uint32_t)(r0 * PX + col) * 2;
                uint32_t o1 = (uint32_t)((r0 + 8) * PX + col) * 2;
                *(uint32_t*)(smem + OFF_X + o0) = pk2(f2h(v0), f2h(v1));
                *(uint32_t*)(smem + OFF_X + o1) = pk2(f2h(v2), f2h(v3));
            }
        }
        __syncthreads();

        // GEMM2: K = 128
        gemm_strip<8>(x, w1, wrow, wcol, lm, acc);

        // write raw h2 = acc + b1 (pre-relu) to smem fp32
#pragma unroll
        for (int m = 0; m < 2; m++) {
            const int r0 = wrow + m * 16 + g;
#pragma unroll
            for (int n = 0; n < 4; n++) {
                const int col = wcol + n * 8 + t * 2;
                const float bx = b1s[col], by = b1s[col + 1];
                h2f[r0 * H2LD + col]           = acc[m][n][0] + bx;
                h2f[r0 * H2LD + col + 1]       = acc[m][n][1] + by;
                h2f[(r0 + 8) * H2LD + col]     = acc[m][n][2] + bx;
                h2f[(r0 + 8) * H2LD + col + 1] = acc[m][n][3] + by;
            }
        }
        __syncthreads();

        // run-reduction scatter: warp w owns cols [w*8, w*8+8);
        // lane = (estart = lid>>3 in 0..3, col = w*8 + (lid&7)).
        // cs[] is sorted -> runs of equal c; flush one atomic per run segment.
        {
            const int col = (wid << 3) + (lid & 7);
            const int estart = lid >> 3;
            int curc = -2;
            float curm = 0.f;
            for (int e = estart; e < TS; e += 4) {
                int c = cs[e];
                float v = h2f[e * H2LD + col];
                if (c != curc) {
                    if (curc >= 0 && curm > 0.f)
                        atomicMax((int*)&g_tmp[(size_t)curc * PAIR + col],
                                  __float_as_int(curm));
                    curc = c;
                    curm = v;
                } else {
                    curm = fmaxf(curm, v);
                }
            }
            if (curc >= 0 && curm > 0.f)
                atomicMax((int*)&g_tmp[(size_t)curc * PAIR + col],
                          __float_as_int(curm));
        }
    }
}

// ---------------------------------------------------------------------------
// Kernel 3: node MLP (R8 fp32 form, 64-node tiles, per-layer weight staging)
// ---------------------------------------------------------------------------
#define NTS 64
#define ACT_LD 132
#define NODE_SMEM_BYTES ((NTS*ACT_LD + PAIR*PAIR) * 4)

__global__ __launch_bounds__(TPB, 1)
void node_kernel(const float* __restrict__ infeats,
                 const float* __restrict__ Wa, const float* __restrict__ ba,
                 const float* __restrict__ Wb, const float* __restrict__ bb_,
                 const float* __restrict__ W2, const float* __restrict__ b2,
                 float* __restrict__ out, int N) {
    extern __shared__ float smemf[];
    float* acts = smemf;
    float* Ws   = smemf + NTS * ACT_LD;

    const int tid = threadIdx.x;
    const int base = blockIdx.x * NTS;
    const int nvalid = min(NTS, N - base);

    for (int idx = tid; idx < NTS * (PAIR / 4); idx += TPB) {
        int node = idx >> 5, k = (idx & 31) * 4;
        float4 v = make_float4(0.f, 0.f, 0.f, 0.f);
        if (node < nvalid) v = *(const float4*)&g_tmp[(size_t)(base + node) * PAIR + k];
        *(float4*)&acts[node * ACT_LD + k] = v;
    }

    const int tx = tid & 15, ty = tid >> 4;
    const int col0 = tx * 8, row0 = ty * 4;

    const float* Wp[3] = {Wa, Wb, W2};
    const float* bp[3] = {ba, bb_, b2};

    for (int layer = 0; layer < 3; layer++) {
        __syncthreads();
        for (int i = tid * 4; i < PAIR * PAIR; i += TPB * 4)
            *(float4*)&Ws[i] = *(const float4*)&Wp[layer][i];
        __syncthreads();

        float acc[4][8];
#pragma unroll
        for (int r = 0; r < 4; r++)
#pragma unroll
            for (int c = 0; c < 8; c++) acc[r][c] = 0.f;

        for (int k = 0; k < PAIR; k += 4) {
            float4 a[4];
#pragma unroll
            for (int r = 0; r < 4; r++)
                a[r] = *(float4*)&acts[(row0 + r) * ACT_LD + k];
#pragma unroll
            for (int kk = 0; kk < 4; kk++) {
                float4 w0 = *(float4*)&Ws[(k + kk) * PAIR + col0];
                float4 w1 = *(float4*)&Ws[(k + kk) * PAIR + col0 + 4];
                float b[8] = {w0.x, w0.y, w0.z, w0.w, w1.x, w1.y, w1.z, w1.w};
#pragma unroll
                for (int r = 0; r < 4; r++) {
                    float av = (kk == 0) ? a[r].x : (kk == 1) ? a[r].y
                             : (kk == 2) ? a[r].z : a[r].w;
#pragma unroll
                    for (int c = 0; c < 8; c++) acc[r][c] += av * b[c];
                }
            }
        }
        __syncthreads();

        float bias[8];
#pragma unroll
        for (int c = 0; c < 8; c++) bias[c] = bp[layer][col0 + c];

        if (layer < 2) {
#pragma unroll
            for (int r = 0; r < 4; r++) {
                float4 v0, v1;
                v0.x = fmaxf(acc[r][0] + bias[0], 0.f);
                v0.y = fmaxf(acc[r][1] + bias[1], 0.f);
                v0.z = fmaxf(acc[r][2] + bias[2], 0.f);
                v0.w = fmaxf(acc[r][3] + bias[3], 0.f);
                v1.x = fmaxf(acc[r][4] + bias[4], 0.f);
                v1.y = fmaxf(acc[r][5] + bias[5], 0.f);
                v1.z = fmaxf(acc[r][6] + bias[6], 0.f);
                v1.w = fmaxf(acc[r][7] + bias[7], 0.f);
                *(float4*)&acts[(row0 + r) * ACT_LD + col0]     = v0;
                *(float4*)&acts[(row0 + r) * ACT_LD + col0 + 4] = v1;
            }
        } else {
#pragma unroll
            for (int r = 0; r < 4; r++) {
                int node = row0 + r;
                if (node < nvalid) {
                    const float* inrow = &infeats[(size_t)(base + node) * SC + col0];
                    float* orow = &out[(size_t)(base + node) * SC + col0];
                    float4 i0 = *(const float4*)&inrow[0];
                    float4 i1 = *(const float4*)&inrow[4];
                    float4 v0, v1;
                    v0.x = fmaxf(acc[r][0] + bias[0] + i0.x, 0.f);
                    v0.y = fmaxf(acc[r][1] + bias[1] + i0.y, 0.f);
                    v0.z = fmaxf(acc[r][2] + bias[2] + i0.z, 0.f);
                    v0.w = fmaxf(acc[r][3] + bias[3] + i0.w, 0.f);
                    v1.x = fmaxf(acc[r][4] + bias[4] + i1.x, 0.f);
                    v1.y = fmaxf(acc[r][5] + bias[5] + i1.y, 0.f);
                    v1.z = fmaxf(acc[r][6] + bias[6] + i1.z, 0.f);
                    v1.w = fmaxf(acc[r][7] + bias[7] + i1.w, 0.f);
                    *(float4*)&orow[0] = v0;
                    *(float4*)&orow[4] = v1;
                }
            }
        }
    }
}

// ---------------------------------------------------------------------------
extern "C" void kernel_launch(void* const* d_in, const int* in_sizes, int n_in,
                              void* d_out, int out_size) {
    const float* infeats = (const float*)d_in[0];
    const float* pw      = (const float*)d_in[1];
    const int*   c_idxs  = (const int*)d_in[2];
    const int*   n_idxs  = (const int*)d_in[3];
    const float* W_rd  = (const float*)d_in[5];
    const float* b_rd  = (const float*)d_in[6];
    const float* W_pw0 = (const float*)d_in[7];
    const float* b_pw0 = (const float*)d_in[8];
    const float* W_pw1 = (const float*)d_in[9];
    const float* b_pw1 = (const float*)d_in[10];
    const float* W_f1a = (const float*)d_in[11];
    const float* b_f1a = (const float*)d_in[12];
    const float* W_f1b = (const float*)d_in[13];
    const float* b_f1b = (const float*)d_in[14];
    const float* W_f2  = (const float*)d_in[15];
    const float* b_f2  = (const float*)d_in[16];
    float* out = (float*)d_out;

    const int N = in_sizes[0] / SC;
    const int E = in_sizes[1] / PWN;

    cudaFuncSetAttribute(edge_kernel, cudaFuncAttributeMaxDynamicSharedMemorySize,
                         EDGE_SMEM_BYTES);
    cudaFuncSetAttribute(node_kernel, cudaFuncAttributeMaxDynamicSharedMemorySize,
                         NODE_SMEM_BYTES);

    const int tot = N * PAIR;
    clear_accum_kernel<<<(tot + 255) / 256, 256>>>(tot, N);

    reduce_kernel<<<(N + 7) / 8, TPB>>>(infeats, W_rd, b_rd, N);

    // counting sort of edges by c
    hist_kernel<<<(E + 255) / 256, 256>>>(c_idxs, E);
    scan_kernel<<<1, 1024>>>(N);
    scatter_kernel<<<(E + 255) / 256, 256>>>(c_idxs, E);

    const int ntiles = (E + TS - 1) / TS;
    const int grid = ntiles < 148 ? ntiles : 148;
    edge_kernel<<<grid, ETPB, EDGE_SMEM_BYTES>>>(pw, c_idxs, n_idxs,
                                                 W_pw0, b_pw0, W_pw1, b_pw1,
                                                 E, ntiles);

    node_kernel<<<(N + NTS - 1) / NTS, TPB, NODE_SMEM_BYTES>>>(
        infeats, W_f1a, b_f1a, W_f1b, b_f1b, W_f2, b_f2, out, N);
}